// round 15
// baseline (speedup 1.0000x reference)
#include <cuda_runtime.h>
#include <cuda_fp16.h>
#include <cstdint>

#define N_NODES 50000
#define N_EDGES 800000
#define FDIM 64
#define INV_AVG_NEIGH (1.0f / 16.0f)

__device__ __align__(16) float g_x[N_NODES * FDIM];
__device__ __align__(16) float g_agg[N_NODES * FDIM];
// fragment-packed fp16 weights, filled by prep_kernel every run (graph-ordered
// before edge_kernel on the same stream)
__device__ __align__(16) uint4 g_w2f[512];    // [4 kt][4 ntp][32 lane]
__device__ __align__(16) uint4 g_bf[2048];    // [16 kt][4 ntp][32 lane]

__device__ __forceinline__ float swishf(float x) {
    return x / (1.0f + __expf(-x));
}
__device__ __forceinline__ float4 fma4(float s, float4 w, float4 acc) {
    acc.x = fmaf(s, w.x, acc.x);
    acc.y = fmaf(s, w.y, acc.y);
    acc.z = fmaf(s, w.z, acc.z);
    acc.w = fmaf(s, w.w, acc.w);
    return acc;
}
// pack two f32 -> f16x2 (lo = a, hi = b)
__device__ __forceinline__ uint32_t h2pack(float a, float b) {
    uint32_t r;
    asm("cvt.rn.f16x2.f32 %0, %1, %2;" : "=r"(r) : "f"(b), "f"(a));
    return r;
}
__device__ __forceinline__ void red_add_f2(float* addr, float v0, float v1) {
    asm volatile("red.global.add.v2.f32 [%0], {%1, %2};"
                 :: "l"(addr), "f"(v0), "f"(v1) : "memory");
}

// mma.sync m16n8k16 f16 row.col, f32 accum
__device__ __forceinline__ void mma_f16(float* d, const uint32_t* a,
                                        uint32_t b0, uint32_t b1) {
    asm volatile(
        "mma.sync.aligned.m16n8k16.row.col.f32.f16.f16.f32 "
        "{%0,%1,%2,%3}, {%4,%5,%6,%7}, {%8,%9}, {%0,%1,%2,%3};"
        : "+f"(d[0]), "+f"(d[1]), "+f"(d[2]), "+f"(d[3])
        : "r"(a[0]), "r"(a[1]), "r"(a[2]), "r"(a[3]), "r"(b0), "r"(b1));
}

__global__ void zero_agg_kernel() {
    int i = blockIdx.x * blockDim.x + threadIdx.x;
    reinterpret_cast<float4*>(g_agg)[i] = make_float4(0.f, 0.f, 0.f, 0.f);
}

// One-time fp16 fragment repack of W2/W3 (identical arithmetic to the r12
// per-CTA staging loops; just computed once instead of 6250 times).
__global__ void prep_kernel(const float* __restrict__ W2,
                            const float* __restrict__ W3) {
    int gid = blockIdx.x * blockDim.x + threadIdx.x;   // 0..2559
    if (gid < 512) {
        int idx = gid;
        int kt = idx >> 7;
        int ntp = (idx >> 5) & 3;
        int ln = idx & 31;
        int gg = ln >> 2, tg = ln & 3;
        uint4 v;
        {
            int n = 8 * (2 * ntp) + gg;
            v.x = h2pack(W2[(16 * kt + 2 * tg) * 64 + n],
                         W2[(16 * kt + 2 * tg + 1) * 64 + n]);
            v.y = h2pack(W2[(16 * kt + 2 * tg + 8) * 64 + n],
                         W2[(16 * kt + 2 * tg + 9) * 64 + n]);
        }
        {
            int n = 8 * (2 * ntp + 1) + gg;
            v.z = h2pack(W2[(16 * kt + 2 * tg) * 64 + n],
                         W2[(16 * kt + 2 * tg + 1) * 64 + n]);
            v.w = h2pack(W2[(16 * kt + 2 * tg + 8) * 64 + n],
                         W2[(16 * kt + 2 * tg + 9) * 64 + n]);
        }
        g_w2f[idx] = v;
    } else if (gid < 2560) {
        int idx = gid - 512;
        int kt = idx >> 7;
        int ntp = (idx >> 5) & 3;
        int ln = idx & 31;
        int gg = ln >> 2, tg = ln & 3;
        int klb = 16 * kt + 2 * tg;
        uint4 v;
#pragma unroll
        for (int s = 0; s < 2; s++) {
            int f = 8 * (2 * ntp + s) + gg;
            uint32_t lo = h2pack(W3[((klb) >> 2) * 256 + 4 * f + (klb & 3)],
                                 W3[((klb + 1) >> 2) * 256 + 4 * f + ((klb + 1) & 3)]);
            uint32_t hi = h2pack(W3[((klb + 8) >> 2) * 256 + 4 * f + ((klb + 8) & 3)],
                                 W3[((klb + 9) >> 2) * 256 + 4 * f + ((klb + 9) & 3)]);
            if (s == 0) { v.x = lo; v.y = hi; } else { v.z = lo; v.w = hi; }
        }
        g_bf[idx] = v;
    }
}

// Y[row,:] = (scale * X[row,:]) @ W  (64x64).
// v2: FOUR threads per row (quarter q computes output cols [16q, 16q+16)).
// Per-output k-accumulation order identical to the 1-thread version ->
// bit-identical results. 200k threads (vs 50k) fixes the grid starvation
// seen at 27us (occ 16%, 2.6 CTAs/SM).
__global__ void linear64_kernel(const float* __restrict__ X,
                                const float* __restrict__ W,
                                float* __restrict__ Y,
                                int n, float scale) {
    __shared__ float4 sW[64 * 16];
    for (int i = threadIdx.x; i < 64 * 16; i += blockDim.x)
        sW[i] = reinterpret_cast<const float4*>(W)[i];
    __syncthreads();

    int t = blockIdx.x * blockDim.x + threadIdx.x;
    int row = t >> 2;
    int q = t & 3;
    if (row >= n) return;

    const float4* xr = reinterpret_cast<const float4*>(X + (size_t)row * 64);
    float xv[64];
#pragma unroll
    for (int i = 0; i < 16; i++) {
        float4 v = xr[i];
        xv[4 * i + 0] = v.x * scale;
        xv[4 * i + 1] = v.y * scale;
        xv[4 * i + 2] = v.z * scale;
        xv[4 * i + 3] = v.w * scale;
    }
    float4 acc[4];
#pragma unroll
    for (int j = 0; j < 4; j++) acc[j] = make_float4(0.f, 0.f, 0.f, 0.f);
#pragma unroll
    for (int k = 0; k < 64; k++) {
        float xk = xv[k];
#pragma unroll
        for (int j = 0; j < 4; j++)
            acc[j] = fma4(xk, sW[k * 16 + 4 * q + j], acc[j]);
    }
    float4* yr = reinterpret_cast<float4*>(Y + (size_t)row * 64 + 16 * q);
#pragma unroll
    for (int j = 0; j < 4; j++) yr[j] = acc[j];
}

// ---------------------------------------------------------------------------
// Fused edge kernel v15 = r14 VERBATIM (validated: 257us, rel_err checksum).
// CTA: 256 threads (8 warps), 128 edges, 3 CTAs/SM (74.75 KB smem).
// ---------------------------------------------------------------------------
#define TILE_E 128
#define NTH 256
#define PADH2 66
// u32-unit offsets
#define OFF_BF  0                        // sBf:  2048 uint4 = 8192 u32
#define OFF_W2F 8192                     // sW2f:  512 uint4 = 2048 u32
#define OFF_H2  (OFF_W2F + 2048)         // sH2: 128*66 = 8448 f32 (sW1 aliased)
#define EDGE_SMEM ((OFF_H2 + 128 * PADH2) * 4)   // 74752 B

__global__ void __launch_bounds__(NTH, 3)
edge_kernel(const float* __restrict__ edge_features,   // [E,4]
            const float* __restrict__ radial,          // [E,8]
            const int* __restrict__ senders,
            const int* __restrict__ receivers,
            const int* __restrict__ mask,               // int32 bool
            const float* __restrict__ W1) {             // [8,64]
    extern __shared__ uint32_t smem[];
    uint4*  sBf  = reinterpret_cast<uint4*>(smem + OFF_BF);    // [16][4][32]
    uint4*  sW2f = reinterpret_cast<uint4*>(smem + OFF_W2F);   // [4][4][32]
    float*  sH2  = reinterpret_cast<float*>(smem + OFF_H2);    // [128][66]
    const float2* sW1f2 = reinterpret_cast<const float2*>(smem + OFF_H2); // alias

    int tid = threadIdx.x;
    int base = blockIdx.x * TILE_E;

    // ---- stage W1 as float2 view (aliased into sH2 head) ----
    {
        float2* w1dst = reinterpret_cast<float2*>(smem + OFF_H2);
        for (int i = tid; i < 256; i += NTH)
            w1dst[i] = reinterpret_cast<const float2*>(W1)[i];
    }
    // ---- coalesced copy of pre-packed fragments ----
    for (int i = tid; i < 2048; i += NTH) sBf[i] = g_bf[i];
    for (int i = tid; i < 512; i += NTH) sW2f[i] = g_w2f[i];
    __syncthreads();

    int w = tid >> 5, lane = tid & 31;
    int g = lane >> 2, tig = lane & 3;
    int row0 = 16 * w + g;
    int e0 = base + row0;
    int e1 = e0 + 8;

    // ---- fused L1: compute h1 at this lane's 16 W2-fragment cols ----
    float rr0[8], rr1[8];
    {
        const float4* rv0 = reinterpret_cast<const float4*>(radial + (size_t)e0 * 8);
        const float4* rv1 = reinterpret_cast<const float4*>(radial + (size_t)e1 * 8);
        float4 p0 = rv0[0], p1 = rv0[1];
        float4 q0 = rv1[0], q1 = rv1[1];
        rr0[0] = p0.x; rr0[1] = p0.y; rr0[2] = p0.z; rr0[3] = p0.w;
        rr0[4] = p1.x; rr0[5] = p1.y; rr0[6] = p1.z; rr0[7] = p1.w;
        rr1[0] = q0.x; rr1[1] = q0.y; rr1[2] = q0.z; rr1[3] = q0.w;
        rr1[4] = q1.x; rr1[5] = q1.y; rr1[6] = q1.z; rr1[7] = q1.w;
    }
    uint32_t A2[4][4];
#pragma unroll
    for (int kt = 0; kt < 4; kt++) {
        float a0x = 0.f, a0y = 0.f, a1x = 0.f, a1y = 0.f;
        float b0x = 0.f, b0y = 0.f, b1x = 0.f, b1y = 0.f;
#pragma unroll
        for (int i = 0; i < 8; i++) {
            float2 wa = sW1f2[i * 32 + 8 * kt + tig];       // cols 16kt+2tig, +1
            float2 wb = sW1f2[i * 32 + 8 * kt + tig + 4];   // cols +8, +9
            a0x = fmaf(rr0[i], wa.x, a0x);
            a0y = fmaf(rr0[i], wa.y, a0y);
            a1x = fmaf(rr1[i], wa.x, a1x);
            a1y = fmaf(rr1[i], wa.y, a1y);
            b0x = fmaf(rr0[i], wb.x, b0x);
            b0y = fmaf(rr0[i], wb.y, b0y);
            b1x = fmaf(rr1[i], wb.x, b1x);
            b1y = fmaf(rr1[i], wb.y, b1y);
        }
        A2[kt][0] = h2pack(swishf(a0x), swishf(a0y));   // row g,   cols c0
        A2[kt][1] = h2pack(swishf(a1x), swishf(a1y));   // row g+8, cols c0
        A2[kt][2] = h2pack(swishf(b0x), swishf(b0y));   // row g,   cols c0+8
        A2[kt][3] = h2pack(swishf(b1x), swishf(b1y));   // row g+8, cols c0+8
    }
    // Barrier: last sW1 read (above) must precede first sH2 write (below),
    // since sW1 aliases sH2 rows 0..7.
    __syncthreads();

    // ================= W2 phase: M=16 per warp, fp16 K=64 =================
    float d2[8][4];
#pragma unroll
    for (int nt = 0; nt < 8; nt++)
#pragma unroll
        for (int q = 0; q < 4; q++) d2[nt][q] = 0.f;

#pragma unroll
    for (int kt = 0; kt < 4; kt++) {
        const uint4* bp = sW2f + kt * 128 + lane;
#pragma unroll
        for (int ntp = 0; ntp < 4; ntp++) {
            uint4 Bv = bp[ntp * 32];
            mma_f16(d2[2 * ntp], A2[kt], Bv.x, Bv.y);
            mma_f16(d2[2 * ntp + 1], A2[kt], Bv.z, Bv.w);
        }
    }
    // swish -> h2 (fp32) to sH2 (warp-private rows)
    {
        float* hw0 = sH2 + row0 * PADH2;
        float* hw1 = hw0 + 8 * PADH2;
#pragma unroll
        for (int nt = 0; nt < 8; nt++) {
            int c = 8 * nt + 2 * tig;
            *reinterpret_cast<float2*>(hw0 + c) =
                make_float2(swishf(d2[nt][0]), swishf(d2[nt][1]));
            *reinterpret_cast<float2*>(hw1 + c) =
                make_float2(swishf(d2[nt][2]), swishf(d2[nt][3]));
        }
    }
    __syncwarp();   // h2 rows produced and consumed by this warp only

    // ================= W3 phase: M=16 per warp, fp16 K=256 =================
    int l0 = 2 * (tig & 1);
    float2 ef0 = *reinterpret_cast<const float2*>(edge_features + (size_t)e0 * 4 + l0);
    float2 ef1 = *reinterpret_cast<const float2*>(edge_features + (size_t)e1 * 4 + l0);
    int snd0 = senders[e0], snd1 = senders[e1];
    int rcv0 = receivers[e0], rcv1 = receivers[e1];
    int mk0 = mask[e0], mk1 = mask[e1];

    float d3[8][4];
#pragma unroll
    for (int nt = 0; nt < 8; nt++)
#pragma unroll
        for (int q = 0; q < 4; q++) d3[nt][q] = 0.f;

    const float* hr0 = sH2 + row0 * PADH2;
    const float* hr1 = hr0 + 8 * PADH2;
    int koff = tig >> 1;
#pragma unroll
    for (int kt = 0; kt < 16; kt++) {
        int k0 = 4 * kt + koff;
        float h00 = hr0[k0];
        float h01 = hr0[k0 + 2];
        float h10 = hr1[k0];
        float h11 = hr1[k0 + 2];
        uint32_t A[4];
        A[0] = h2pack(h00 * ef0.x, h00 * ef0.y);   // row g,   k0, l pair
        A[1] = h2pack(h10 * ef1.x, h10 * ef1.y);   // row g+8, k0
        A[2] = h2pack(h01 * ef0.x, h01 * ef0.y);   // row g,   k1
        A[3] = h2pack(h11 * ef1.x, h11 * ef1.y);   // row g+8, k1
        const uint4* bp = sBf + kt * 128 + lane;
#pragma unroll
        for (int ntp = 0; ntp < 4; ntp++) {
            uint4 Bv = bp[ntp * 32];
            mma_f16(d3[2 * ntp], A, Bv.x, Bv.y);
            mma_f16(d3[2 * ntp + 1], A, Bv.z, Bv.w);
        }
    }

    // ---- epilogue (r9/r12 v2): msg = d3 * x[snd], red-scatter ----
    if (mk0) {
        const float* xr = g_x + (size_t)snd0 * 64;
        float* ar = g_agg + (size_t)rcv0 * 64;
#pragma unroll
        for (int nt = 0; nt < 8; nt++) {
            int c = 8 * nt + 2 * tig;
            float2 xs = *reinterpret_cast<const float2*>(xr + c);
            red_add_f2(ar + c, d3[nt][0] * xs.x, d3[nt][1] * xs.y);
        }
    }
    if (mk1) {
        const float* xr = g_x + (size_t)snd1 * 64;
        float* ar = g_agg + (size_t)rcv1 * 64;
#pragma unroll
        for (int nt = 0; nt < 8; nt++) {
            int c = 8 * nt + 2 * tig;
            float2 xs = *reinterpret_cast<const float2*>(xr + c);
            red_add_f2(ar + c, d3[nt][2] * xs.x, d3[nt][3] * xs.y);
        }
    }
}

// ---------------------------------------------------------------------------
// kernel_launch — edge_kernel at launch index 3 (profiler sample position);
// prep_kernel at idx 2, same stream => ordered before edge.
// ---------------------------------------------------------------------------
extern "C" void kernel_launch(void* const* d_in, const int* in_sizes, int n_in,
                              void* d_out, int out_size) {
    const float* node_features = (const float*)d_in[0];
    const float* edge_features = (const float*)d_in[1];
    const float* radial        = (const float*)d_in[2];
    const int*   senders       = (const int*)d_in[3];
    const int*   receivers     = (const int*)d_in[4];
    const int*   edge_mask     = (const int*)d_in[5];
    const float* W_up          = (const float*)d_in[6];
    const float* W1            = (const float*)d_in[7];
    const float* W2            = (const float*)d_in[8];
    const float* W3            = (const float*)d_in[9];
    const float* W_down        = (const float*)d_in[10];
    float*       out           = (float*)d_out;

    float* x_ptr = nullptr;
    float* agg_ptr = nullptr;
    cudaGetSymbolAddress((void**)&x_ptr, g_x);
    cudaGetSymbolAddress((void**)&agg_ptr, g_agg);

    // idx 0: x = node_features @ W_up   (4 threads/row: 200k threads)
    linear64_kernel<<<(4 * N_NODES + 255) / 256, 256>>>(node_features, W_up,
                                                        x_ptr, N_NODES, 1.0f);
    // idx 1: zero agg
    zero_agg_kernel<<<(N_NODES * FDIM / 4) / 256, 256>>>();
    // idx 2: one-time fp16 fragment repack (ordered before edge on stream)
    prep_kernel<<<5, 512>>>(W2, W3);
    // idx 3: fused edge kernel  <-- profiler sample position
    cudaFuncSetAttribute(edge_kernel, cudaFuncAttributeMaxDynamicSharedMemorySize,
                         EDGE_SMEM);
    edge_kernel<<<N_EDGES / TILE_E, NTH, EDGE_SMEM>>>(
        edge_features, radial, senders, receivers, edge_mask, W1);
    // idx 4: out = (agg / 16) @ W_down  (4 threads/row)
    linear64_kernel<<<(4 * N_NODES + 255) / 256, 256>>>(agg_ptr, W_down, out,
                                                        N_NODES, INV_AVG_NEIGH);
}

// round 16
// speedup vs baseline: 1.2365x; 1.2365x over previous
#include <cuda_runtime.h>
#include <cuda_fp16.h>
#include <cstdint>

#define N_NODES 50000
#define N_EDGES 800000
#define FDIM 64
#define INV_AVG_NEIGH (1.0f / 16.0f)

__device__ __align__(16) float g_x[N_NODES * FDIM];
__device__ __align__(16) float g_agg[N_NODES * FDIM];
// fragment-packed fp16 weights, filled by prep_kernel every run (graph-ordered
// before edge_kernel on the same stream)
__device__ __align__(16) uint4 g_w2f[512];    // [4 kt][4 ntp][32 lane]
__device__ __align__(16) uint4 g_bf[2048];    // [16 kt][4 ntp][32 lane]

__device__ __forceinline__ float swishf(float x) {
    return x / (1.0f + __expf(-x));
}
__device__ __forceinline__ float4 fma4(float s, float4 w, float4 acc) {
    acc.x = fmaf(s, w.x, acc.x);
    acc.y = fmaf(s, w.y, acc.y);
    acc.z = fmaf(s, w.z, acc.z);
    acc.w = fmaf(s, w.w, acc.w);
    return acc;
}
// pack two f32 -> f16x2 (lo = a, hi = b)
__device__ __forceinline__ uint32_t h2pack(float a, float b) {
    uint32_t r;
    asm("cvt.rn.f16x2.f32 %0, %1, %2;" : "=r"(r) : "f"(b), "f"(a));
    return r;
}
__device__ __forceinline__ void red_add_f2(float* addr, float v0, float v1) {
    asm volatile("red.global.add.v2.f32 [%0], {%1, %2};"
                 :: "l"(addr), "f"(v0), "f"(v1) : "memory");
}

// mma.sync m16n8k16 f16 row.col, f32 accum
__device__ __forceinline__ void mma_f16(float* d, const uint32_t* a,
                                        uint32_t b0, uint32_t b1) {
    asm volatile(
        "mma.sync.aligned.m16n8k16.row.col.f32.f16.f16.f32 "
        "{%0,%1,%2,%3}, {%4,%5,%6,%7}, {%8,%9}, {%0,%1,%2,%3};"
        : "+f"(d[0]), "+f"(d[1]), "+f"(d[2]), "+f"(d[3])
        : "r"(a[0]), "r"(a[1]), "r"(a[2]), "r"(a[3]), "r"(b0), "r"(b1));
}

__global__ void zero_agg_kernel() {
    int i = blockIdx.x * blockDim.x + threadIdx.x;
    reinterpret_cast<float4*>(g_agg)[i] = make_float4(0.f, 0.f, 0.f, 0.f);
}

// One-time fp16 fragment repack of W2/W3 (identical arithmetic to the r12
// per-CTA staging loops; computed once instead of 6250 times).
__global__ void prep_kernel(const float* __restrict__ W2,
                            const float* __restrict__ W3) {
    int gid = blockIdx.x * blockDim.x + threadIdx.x;   // 0..2559
    if (gid < 512) {
        int idx = gid;
        int kt = idx >> 7;
        int ntp = (idx >> 5) & 3;
        int ln = idx & 31;
        int gg = ln >> 2, tg = ln & 3;
        uint4 v;
        {
            int n = 8 * (2 * ntp) + gg;
            v.x = h2pack(W2[(16 * kt + 2 * tg) * 64 + n],
                         W2[(16 * kt + 2 * tg + 1) * 64 + n]);
            v.y = h2pack(W2[(16 * kt + 2 * tg + 8) * 64 + n],
                         W2[(16 * kt + 2 * tg + 9) * 64 + n]);
        }
        {
            int n = 8 * (2 * ntp + 1) + gg;
            v.z = h2pack(W2[(16 * kt + 2 * tg) * 64 + n],
                         W2[(16 * kt + 2 * tg + 1) * 64 + n]);
            v.w = h2pack(W2[(16 * kt + 2 * tg + 8) * 64 + n],
                         W2[(16 * kt + 2 * tg + 9) * 64 + n]);
        }
        g_w2f[idx] = v;
    } else if (gid < 2560) {
        int idx = gid - 512;
        int kt = idx >> 7;
        int ntp = (idx >> 5) & 3;
        int ln = idx & 31;
        int gg = ln >> 2, tg = ln & 3;
        int klb = 16 * kt + 2 * tg;
        uint4 v;
#pragma unroll
        for (int s = 0; s < 2; s++) {
            int f = 8 * (2 * ntp + s) + gg;
            uint32_t lo = h2pack(W3[((klb) >> 2) * 256 + 4 * f + (klb & 3)],
                                 W3[((klb + 1) >> 2) * 256 + 4 * f + ((klb + 1) & 3)]);
            uint32_t hi = h2pack(W3[((klb + 8) >> 2) * 256 + 4 * f + ((klb + 8) & 3)],
                                 W3[((klb + 9) >> 2) * 256 + 4 * f + ((klb + 9) & 3)]);
            if (s == 0) { v.x = lo; v.y = hi; } else { v.z = lo; v.w = hi; }
        }
        g_bf[idx] = v;
    }
}

// Y[row,:] = (scale * X[row,:]) @ W  (64x64). One row per thread (r14
// decomposition: all-lanes-broadcast sW reads, 1x X traffic), but x is
// STREAMED 4 k at a time instead of preloaded into xv[64] — removes 64
// registers (115 -> ~75) to roughly double residency. Identical k order and
// op sequence -> bit-identical results (rel_err checksum 3.898827e-4).
__global__ void linear64_kernel(const float* __restrict__ X,
                                const float* __restrict__ W,
                                float* __restrict__ Y,
                                int n, float scale) {
    __shared__ float4 sW[64 * 16];
    for (int i = threadIdx.x; i < 64 * 16; i += blockDim.x)
        sW[i] = reinterpret_cast<const float4*>(W)[i];
    __syncthreads();

    int row = blockIdx.x * blockDim.x + threadIdx.x;
    if (row >= n) return;

    const float4* xr = reinterpret_cast<const float4*>(X + (size_t)row * 64);
    float4 acc[16];
#pragma unroll
    for (int j = 0; j < 16; j++) acc[j] = make_float4(0.f, 0.f, 0.f, 0.f);

#pragma unroll
    for (int i = 0; i < 16; i++) {
        float4 v = xr[i];
        float x0 = v.x * scale;
        float x1 = v.y * scale;
        float x2 = v.z * scale;
        float x3 = v.w * scale;
        const float4* w0 = sW + (4 * i) * 16;
#pragma unroll
        for (int j = 0; j < 16; j++) acc[j] = fma4(x0, w0[j], acc[j]);
#pragma unroll
        for (int j = 0; j < 16; j++) acc[j] = fma4(x1, w0[16 + j], acc[j]);
#pragma unroll
        for (int j = 0; j < 16; j++) acc[j] = fma4(x2, w0[32 + j], acc[j]);
#pragma unroll
        for (int j = 0; j < 16; j++) acc[j] = fma4(x3, w0[48 + j], acc[j]);
    }
    float4* yr = reinterpret_cast<float4*>(Y + (size_t)row * 64);
#pragma unroll
    for (int j = 0; j < 16; j++) yr[j] = acc[j];
}

// ---------------------------------------------------------------------------
// Fused edge kernel v16 = r14 VERBATIM (validated: 257us, rel_err checksum).
// CTA: 256 threads (8 warps), 128 edges, 3 CTAs/SM (74.75 KB smem).
// ---------------------------------------------------------------------------
#define TILE_E 128
#define NTH 256
#define PADH2 66
// u32-unit offsets
#define OFF_BF  0                        // sBf:  2048 uint4 = 8192 u32
#define OFF_W2F 8192                     // sW2f:  512 uint4 = 2048 u32
#define OFF_H2  (OFF_W2F + 2048)         // sH2: 128*66 = 8448 f32 (sW1 aliased)
#define EDGE_SMEM ((OFF_H2 + 128 * PADH2) * 4)   // 74752 B

__global__ void __launch_bounds__(NTH, 3)
edge_kernel(const float* __restrict__ edge_features,   // [E,4]
            const float* __restrict__ radial,          // [E,8]
            const int* __restrict__ senders,
            const int* __restrict__ receivers,
            const int* __restrict__ mask,               // int32 bool
            const float* __restrict__ W1) {             // [8,64]
    extern __shared__ uint32_t smem[];
    uint4*  sBf  = reinterpret_cast<uint4*>(smem + OFF_BF);    // [16][4][32]
    uint4*  sW2f = reinterpret_cast<uint4*>(smem + OFF_W2F);   // [4][4][32]
    float*  sH2  = reinterpret_cast<float*>(smem + OFF_H2);    // [128][66]
    const float2* sW1f2 = reinterpret_cast<const float2*>(smem + OFF_H2); // alias

    int tid = threadIdx.x;
    int base = blockIdx.x * TILE_E;

    // ---- stage W1 as float2 view (aliased into sH2 head) ----
    {
        float2* w1dst = reinterpret_cast<float2*>(smem + OFF_H2);
        for (int i = tid; i < 256; i += NTH)
            w1dst[i] = reinterpret_cast<const float2*>(W1)[i];
    }
    // ---- coalesced copy of pre-packed fragments ----
    for (int i = tid; i < 2048; i += NTH) sBf[i] = g_bf[i];
    for (int i = tid; i < 512; i += NTH) sW2f[i] = g_w2f[i];
    __syncthreads();

    int w = tid >> 5, lane = tid & 31;
    int g = lane >> 2, tig = lane & 3;
    int row0 = 16 * w + g;
    int e0 = base + row0;
    int e1 = e0 + 8;

    // ---- fused L1: compute h1 at this lane's 16 W2-fragment cols ----
    float rr0[8], rr1[8];
    {
        const float4* rv0 = reinterpret_cast<const float4*>(radial + (size_t)e0 * 8);
        const float4* rv1 = reinterpret_cast<const float4*>(radial + (size_t)e1 * 8);
        float4 p0 = rv0[0], p1 = rv0[1];
        float4 q0 = rv1[0], q1 = rv1[1];
        rr0[0] = p0.x; rr0[1] = p0.y; rr0[2] = p0.z; rr0[3] = p0.w;
        rr0[4] = p1.x; rr0[5] = p1.y; rr0[6] = p1.z; rr0[7] = p1.w;
        rr1[0] = q0.x; rr1[1] = q0.y; rr1[2] = q0.z; rr1[3] = q0.w;
        rr1[4] = q1.x; rr1[5] = q1.y; rr1[6] = q1.z; rr1[7] = q1.w;
    }
    uint32_t A2[4][4];
#pragma unroll
    for (int kt = 0; kt < 4; kt++) {
        float a0x = 0.f, a0y = 0.f, a1x = 0.f, a1y = 0.f;
        float b0x = 0.f, b0y = 0.f, b1x = 0.f, b1y = 0.f;
#pragma unroll
        for (int i = 0; i < 8; i++) {
            float2 wa = sW1f2[i * 32 + 8 * kt + tig];       // cols 16kt+2tig, +1
            float2 wb = sW1f2[i * 32 + 8 * kt + tig + 4];   // cols +8, +9
            a0x = fmaf(rr0[i], wa.x, a0x);
            a0y = fmaf(rr0[i], wa.y, a0y);
            a1x = fmaf(rr1[i], wa.x, a1x);
            a1y = fmaf(rr1[i], wa.y, a1y);
            b0x = fmaf(rr0[i], wb.x, b0x);
            b0y = fmaf(rr0[i], wb.y, b0y);
            b1x = fmaf(rr1[i], wb.x, b1x);
            b1y = fmaf(rr1[i], wb.y, b1y);
        }
        A2[kt][0] = h2pack(swishf(a0x), swishf(a0y));   // row g,   cols c0
        A2[kt][1] = h2pack(swishf(a1x), swishf(a1y));   // row g+8, cols c0
        A2[kt][2] = h2pack(swishf(b0x), swishf(b0y));   // row g,   cols c0+8
        A2[kt][3] = h2pack(swishf(b1x), swishf(b1y));   // row g+8, cols c0+8
    }
    // Barrier: last sW1 read (above) must precede first sH2 write (below),
    // since sW1 aliases sH2 rows 0..7.
    __syncthreads();

    // ================= W2 phase: M=16 per warp, fp16 K=64 =================
    float d2[8][4];
#pragma unroll
    for (int nt = 0; nt < 8; nt++)
#pragma unroll
        for (int q = 0; q < 4; q++) d2[nt][q] = 0.f;

#pragma unroll
    for (int kt = 0; kt < 4; kt++) {
        const uint4* bp = sW2f + kt * 128 + lane;
#pragma unroll
        for (int ntp = 0; ntp < 4; ntp++) {
            uint4 Bv = bp[ntp * 32];
            mma_f16(d2[2 * ntp], A2[kt], Bv.x, Bv.y);
            mma_f16(d2[2 * ntp + 1], A2[kt], Bv.z, Bv.w);
        }
    }
    // swish -> h2 (fp32) to sH2 (warp-private rows)
    {
        float* hw0 = sH2 + row0 * PADH2;
        float* hw1 = hw0 + 8 * PADH2;
#pragma unroll
        for (int nt = 0; nt < 8; nt++) {
            int c = 8 * nt + 2 * tig;
            *reinterpret_cast<float2*>(hw0 + c) =
                make_float2(swishf(d2[nt][0]), swishf(d2[nt][1]));
            *reinterpret_cast<float2*>(hw1 + c) =
                make_float2(swishf(d2[nt][2]), swishf(d2[nt][3]));
        }
    }
    __syncwarp();   // h2 rows produced and consumed by this warp only

    // ================= W3 phase: M=16 per warp, fp16 K=256 =================
    int l0 = 2 * (tig & 1);
    float2 ef0 = *reinterpret_cast<const float2*>(edge_features + (size_t)e0 * 4 + l0);
    float2 ef1 = *reinterpret_cast<const float2*>(edge_features + (size_t)e1 * 4 + l0);
    int snd0 = senders[e0], snd1 = senders[e1];
    int rcv0 = receivers[e0], rcv1 = receivers[e1];
    int mk0 = mask[e0], mk1 = mask[e1];

    float d3[8][4];
#pragma unroll
    for (int nt = 0; nt < 8; nt++)
#pragma unroll
        for (int q = 0; q < 4; q++) d3[nt][q] = 0.f;

    const float* hr0 = sH2 + row0 * PADH2;
    const float* hr1 = hr0 + 8 * PADH2;
    int koff = tig >> 1;
#pragma unroll
    for (int kt = 0; kt < 16; kt++) {
        int k0 = 4 * kt + koff;
        float h00 = hr0[k0];
        float h01 = hr0[k0 + 2];
        float h10 = hr1[k0];
        float h11 = hr1[k0 + 2];
        uint32_t A[4];
        A[0] = h2pack(h00 * ef0.x, h00 * ef0.y);   // row g,   k0, l pair
        A[1] = h2pack(h10 * ef1.x, h10 * ef1.y);   // row g+8, k0
        A[2] = h2pack(h01 * ef0.x, h01 * ef0.y);   // row g,   k1
        A[3] = h2pack(h11 * ef1.x, h11 * ef1.y);   // row g+8, k1
        const uint4* bp = sBf + kt * 128 + lane;
#pragma unroll
        for (int ntp = 0; ntp < 4; ntp++) {
            uint4 Bv = bp[ntp * 32];
            mma_f16(d3[2 * ntp], A, Bv.x, Bv.y);
            mma_f16(d3[2 * ntp + 1], A, Bv.z, Bv.w);
        }
    }

    // ---- epilogue (r9/r12 v2): msg = d3 * x[snd], red-scatter ----
    if (mk0) {
        const float* xr = g_x + (size_t)snd0 * 64;
        float* ar = g_agg + (size_t)rcv0 * 64;
#pragma unroll
        for (int nt = 0; nt < 8; nt++) {
            int c = 8 * nt + 2 * tig;
            float2 xs = *reinterpret_cast<const float2*>(xr + c);
            red_add_f2(ar + c, d3[nt][0] * xs.x, d3[nt][1] * xs.y);
        }
    }
    if (mk1) {
        const float* xr = g_x + (size_t)snd1 * 64;
        float* ar = g_agg + (size_t)rcv1 * 64;
#pragma unroll
        for (int nt = 0; nt < 8; nt++) {
            int c = 8 * nt + 2 * tig;
            float2 xs = *reinterpret_cast<const float2*>(xr + c);
            red_add_f2(ar + c, d3[nt][2] * xs.x, d3[nt][3] * xs.y);
        }
    }
}

// ---------------------------------------------------------------------------
// kernel_launch — edge_kernel at launch index 3 (profiler sample position);
// prep_kernel at idx 2, same stream => ordered before edge.
// ---------------------------------------------------------------------------
extern "C" void kernel_launch(void* const* d_in, const int* in_sizes, int n_in,
                              void* d_out, int out_size) {
    const float* node_features = (const float*)d_in[0];
    const float* edge_features = (const float*)d_in[1];
    const float* radial        = (const float*)d_in[2];
    const int*   senders       = (const int*)d_in[3];
    const int*   receivers     = (const int*)d_in[4];
    const int*   edge_mask     = (const int*)d_in[5];
    const float* W_up          = (const float*)d_in[6];
    const float* W1            = (const float*)d_in[7];
    const float* W2            = (const float*)d_in[8];
    const float* W3            = (const float*)d_in[9];
    const float* W_down        = (const float*)d_in[10];
    float*       out           = (float*)d_out;

    float* x_ptr = nullptr;
    float* agg_ptr = nullptr;
    cudaGetSymbolAddress((void**)&x_ptr, g_x);
    cudaGetSymbolAddress((void**)&agg_ptr, g_agg);

    // idx 0: x = node_features @ W_up   (1 thread/row, streamed x)
    linear64_kernel<<<(N_NODES + 127) / 128, 128>>>(node_features, W_up, x_ptr,
                                                    N_NODES, 1.0f);
    // idx 1: zero agg
    zero_agg_kernel<<<(N_NODES * FDIM / 4) / 256, 256>>>();
    // idx 2: one-time fp16 fragment repack (ordered before edge on stream)
    prep_kernel<<<5, 512>>>(W2, W3);
    // idx 3: fused edge kernel  <-- profiler sample position
    cudaFuncSetAttribute(edge_kernel, cudaFuncAttributeMaxDynamicSharedMemorySize,
                         EDGE_SMEM);
    edge_kernel<<<N_EDGES / TILE_E, NTH, EDGE_SMEM>>>(
        edge_features, radial, senders, receivers, edge_mask, W1);
    // idx 4: out = (agg / 16) @ W_down  (1 thread/row, streamed x)
    linear64_kernel<<<(N_NODES + 127) / 128, 128>>>(agg_ptr, W_down, out,
                                                    N_NODES, INV_AVG_NEIGH);
}

// round 17
// speedup vs baseline: 1.2697x; 1.0269x over previous
#include <cuda_runtime.h>
#include <cuda_fp16.h>
#include <cstdint>

#define N_NODES 50000
#define N_EDGES 800000
#define FDIM 64
#define INV_AVG_NEIGH (1.0f / 16.0f)

__device__ __align__(16) float g_x[N_NODES * FDIM];
__device__ __align__(16) float g_agg[N_NODES * FDIM];
// fragment-packed fp16 weights, filled by prep_kernel every run (graph-ordered
// before edge_kernel on the same stream)
__device__ __align__(16) uint4 g_w2f[512];    // [4 kt][4 ntp][32 lane]
__device__ __align__(16) uint4 g_bf[2048];    // [16 kt][4 ntp][32 lane]

__device__ __forceinline__ float swishf(float x) {
    return x / (1.0f + __expf(-x));
}
__device__ __forceinline__ float4 fma4(float s, float4 w, float4 acc) {
    acc.x = fmaf(s, w.x, acc.x);
    acc.y = fmaf(s, w.y, acc.y);
    acc.z = fmaf(s, w.z, acc.z);
    acc.w = fmaf(s, w.w, acc.w);
    return acc;
}
// pack two f32 -> f16x2 (lo = a, hi = b)
__device__ __forceinline__ uint32_t h2pack(float a, float b) {
    uint32_t r;
    asm("cvt.rn.f16x2.f32 %0, %1, %2;" : "=r"(r) : "f"(b), "f"(a));
    return r;
}
__device__ __forceinline__ void red_add_f2(float* addr, float v0, float v1) {
    asm volatile("red.global.add.v2.f32 [%0], {%1, %2};"
                 :: "l"(addr), "f"(v0), "f"(v1) : "memory");
}

// mma.sync m16n8k16 f16 row.col, f32 accum
__device__ __forceinline__ void mma_f16(float* d, const uint32_t* a,
                                        uint32_t b0, uint32_t b1) {
    asm volatile(
        "mma.sync.aligned.m16n8k16.row.col.f32.f16.f16.f32 "
        "{%0,%1,%2,%3}, {%4,%5,%6,%7}, {%8,%9}, {%0,%1,%2,%3};"
        : "+f"(d[0]), "+f"(d[1]), "+f"(d[2]), "+f"(d[3])
        : "r"(a[0]), "r"(a[1]), "r"(a[2]), "r"(a[3]), "r"(b0), "r"(b1));
}

__global__ void zero_agg_kernel() {
    int i = blockIdx.x * blockDim.x + threadIdx.x;
    reinterpret_cast<float4*>(g_agg)[i] = make_float4(0.f, 0.f, 0.f, 0.f);
}

// One-time fp16 fragment repack of W2/W3 (identical arithmetic to the r12
// per-CTA staging loops; computed once instead of per-CTA).
__global__ void prep_kernel(const float* __restrict__ W2,
                            const float* __restrict__ W3) {
    int gid = blockIdx.x * blockDim.x + threadIdx.x;   // 0..2559
    if (gid < 512) {
        int idx = gid;
        int kt = idx >> 7;
        int ntp = (idx >> 5) & 3;
        int ln = idx & 31;
        int gg = ln >> 2, tg = ln & 3;
        uint4 v;
        {
            int n = 8 * (2 * ntp) + gg;
            v.x = h2pack(W2[(16 * kt + 2 * tg) * 64 + n],
                         W2[(16 * kt + 2 * tg + 1) * 64 + n]);
            v.y = h2pack(W2[(16 * kt + 2 * tg + 8) * 64 + n],
                         W2[(16 * kt + 2 * tg + 9) * 64 + n]);
        }
        {
            int n = 8 * (2 * ntp + 1) + gg;
            v.z = h2pack(W2[(16 * kt + 2 * tg) * 64 + n],
                         W2[(16 * kt + 2 * tg + 1) * 64 + n]);
            v.w = h2pack(W2[(16 * kt + 2 * tg + 8) * 64 + n],
                         W2[(16 * kt + 2 * tg + 9) * 64 + n]);
        }
        g_w2f[idx] = v;
    } else if (gid < 2560) {
        int idx = gid - 512;
        int kt = idx >> 7;
        int ntp = (idx >> 5) & 3;
        int ln = idx & 31;
        int gg = ln >> 2, tg = ln & 3;
        int klb = 16 * kt + 2 * tg;
        uint4 v;
#pragma unroll
        for (int s = 0; s < 2; s++) {
            int f = 8 * (2 * ntp + s) + gg;
            uint32_t lo = h2pack(W3[((klb) >> 2) * 256 + 4 * f + (klb & 3)],
                                 W3[((klb + 1) >> 2) * 256 + 4 * f + ((klb + 1) & 3)]);
            uint32_t hi = h2pack(W3[((klb + 8) >> 2) * 256 + 4 * f + ((klb + 8) & 3)],
                                 W3[((klb + 9) >> 2) * 256 + 4 * f + ((klb + 9) & 3)]);
            if (s == 0) { v.x = lo; v.y = hi; } else { v.z = lo; v.w = hi; }
        }
        g_bf[idx] = v;
    }
}

// Y[row,:] = (scale * X[row,:]) @ W  (64x64). One row per thread, x streamed
// (r16, validated neutral/correct).
__global__ void linear64_kernel(const float* __restrict__ X,
                                const float* __restrict__ W,
                                float* __restrict__ Y,
                                int n, float scale) {
    __shared__ float4 sW[64 * 16];
    for (int i = threadIdx.x; i < 64 * 16; i += blockDim.x)
        sW[i] = reinterpret_cast<const float4*>(W)[i];
    __syncthreads();

    int row = blockIdx.x * blockDim.x + threadIdx.x;
    if (row >= n) return;

    const float4* xr = reinterpret_cast<const float4*>(X + (size_t)row * 64);
    float4 acc[16];
#pragma unroll
    for (int j = 0; j < 16; j++) acc[j] = make_float4(0.f, 0.f, 0.f, 0.f);

#pragma unroll
    for (int i = 0; i < 16; i++) {
        float4 v = xr[i];
        float x0 = v.x * scale;
        float x1 = v.y * scale;
        float x2 = v.z * scale;
        float x3 = v.w * scale;
        const float4* w0 = sW + (4 * i) * 16;
#pragma unroll
        for (int j = 0; j < 16; j++) acc[j] = fma4(x0, w0[j], acc[j]);
#pragma unroll
        for (int j = 0; j < 16; j++) acc[j] = fma4(x1, w0[16 + j], acc[j]);
#pragma unroll
        for (int j = 0; j < 16; j++) acc[j] = fma4(x2, w0[32 + j], acc[j]);
#pragma unroll
        for (int j = 0; j < 16; j++) acc[j] = fma4(x3, w0[48 + j], acc[j]);
    }
    float4* yr = reinterpret_cast<float4*>(Y + (size_t)row * 64);
#pragma unroll
    for (int j = 0; j < 16; j++) yr[j] = acc[j];
}

// ---------------------------------------------------------------------------
// Fused edge kernel v17 = r14/r16 mainloop, MULTI-TILE: each CTA processes
// TILES=5 consecutive 128-edge tiles, staging the 40KB W2/W3 fragments ONCE
// (was per-128-edges: 250 MB of L2 staging traffic chip-wide -> 50 MB).
// W1 (2KB, aliases sH2 head, clobbered by each tile's h2 writes) is re-staged
// per tile from L2 — trivial. Per-edge arithmetic/order unchanged ->
// rel_err checksum ~3.898828e-4.
// CTA: 256 threads (8 warps), 3 CTAs/SM (74.75 KB smem), grid 1250.
// ---------------------------------------------------------------------------
#define TILE_E 128
#define TILES 5
#define NTH 256
#define PADH2 66
// u32-unit offsets
#define OFF_BF  0                        // sBf:  2048 uint4 = 8192 u32
#define OFF_W2F 8192                     // sW2f:  512 uint4 = 2048 u32
#define OFF_H2  (OFF_W2F + 2048)         // sH2: 128*66 = 8448 f32 (sW1 aliased)
#define EDGE_SMEM ((OFF_H2 + 128 * PADH2) * 4)   // 74752 B

__global__ void __launch_bounds__(NTH, 3)
edge_kernel(const float* __restrict__ edge_features,   // [E,4]
            const float* __restrict__ radial,          // [E,8]
            const int* __restrict__ senders,
            const int* __restrict__ receivers,
            const int* __restrict__ mask,               // int32 bool
            const float* __restrict__ W1) {             // [8,64]
    extern __shared__ uint32_t smem[];
    uint4*  sBf  = reinterpret_cast<uint4*>(smem + OFF_BF);    // [16][4][32]
    uint4*  sW2f = reinterpret_cast<uint4*>(smem + OFF_W2F);   // [4][4][32]
    float*  sH2  = reinterpret_cast<float*>(smem + OFF_H2);    // [128][66]
    const float2* sW1f2 = reinterpret_cast<const float2*>(smem + OFF_H2); // alias

    int tid = threadIdx.x;

    // ---- coalesced copy of pre-packed fragments (ONCE per CTA) ----
    for (int i = tid; i < 2048; i += NTH) sBf[i] = g_bf[i];
    for (int i = tid; i < 512; i += NTH) sW2f[i] = g_w2f[i];

    int w = tid >> 5, lane = tid & 31;
    int g = lane >> 2, tig = lane & 3;
    int row0 = 16 * w + g;
    int cta_base = blockIdx.x * (TILE_E * TILES);

#pragma unroll 1
    for (int t = 0; t < TILES; t++) {
        // Barrier: (t=0) fragments staged; (t>0) prior tile's sH2 reads done
        // before W1 staging overwrites sH2 rows 0..7.
        __syncthreads();
        // ---- stage W1 (float2 view, aliased into sH2 head) ----
        {
            float2* w1dst = reinterpret_cast<float2*>(smem + OFF_H2);
            for (int i = tid; i < 256; i += NTH)
                w1dst[i] = reinterpret_cast<const float2*>(W1)[i];
        }
        __syncthreads();

        int base = cta_base + t * TILE_E;
        int e0 = base + row0;
        int e1 = e0 + 8;

        // ---- fused L1: compute h1 at this lane's 16 W2-fragment cols ----
        float rr0[8], rr1[8];
        {
            const float4* rv0 = reinterpret_cast<const float4*>(radial + (size_t)e0 * 8);
            const float4* rv1 = reinterpret_cast<const float4*>(radial + (size_t)e1 * 8);
            float4 p0 = rv0[0], p1 = rv0[1];
            float4 q0 = rv1[0], q1 = rv1[1];
            rr0[0] = p0.x; rr0[1] = p0.y; rr0[2] = p0.z; rr0[3] = p0.w;
            rr0[4] = p1.x; rr0[5] = p1.y; rr0[6] = p1.z; rr0[7] = p1.w;
            rr1[0] = q0.x; rr1[1] = q0.y; rr1[2] = q0.z; rr1[3] = q0.w;
            rr1[4] = q1.x; rr1[5] = q1.y; rr1[6] = q1.z; rr1[7] = q1.w;
        }
        uint32_t A2[4][4];
#pragma unroll
        for (int kt = 0; kt < 4; kt++) {
            float a0x = 0.f, a0y = 0.f, a1x = 0.f, a1y = 0.f;
            float b0x = 0.f, b0y = 0.f, b1x = 0.f, b1y = 0.f;
#pragma unroll
            for (int i = 0; i < 8; i++) {
                float2 wa = sW1f2[i * 32 + 8 * kt + tig];       // cols 16kt+2tig, +1
                float2 wb = sW1f2[i * 32 + 8 * kt + tig + 4];   // cols +8, +9
                a0x = fmaf(rr0[i], wa.x, a0x);
                a0y = fmaf(rr0[i], wa.y, a0y);
                a1x = fmaf(rr1[i], wa.x, a1x);
                a1y = fmaf(rr1[i], wa.y, a1y);
                b0x = fmaf(rr0[i], wb.x, b0x);
                b0y = fmaf(rr0[i], wb.y, b0y);
                b1x = fmaf(rr1[i], wb.x, b1x);
                b1y = fmaf(rr1[i], wb.y, b1y);
            }
            A2[kt][0] = h2pack(swishf(a0x), swishf(a0y));   // row g,   cols c0
            A2[kt][1] = h2pack(swishf(a1x), swishf(a1y));   // row g+8, cols c0
            A2[kt][2] = h2pack(swishf(b0x), swishf(b0y));   // row g,   cols c0+8
            A2[kt][3] = h2pack(swishf(b1x), swishf(b1y));   // row g+8, cols c0+8
        }
        // Barrier: last sW1 read (above) must precede first sH2 write (below).
        __syncthreads();

        // ============== W2 phase: M=16 per warp, fp16 K=64 ==============
        float d2[8][4];
#pragma unroll
        for (int nt = 0; nt < 8; nt++)
#pragma unroll
            for (int q = 0; q < 4; q++) d2[nt][q] = 0.f;

#pragma unroll
        for (int kt = 0; kt < 4; kt++) {
            const uint4* bp = sW2f + kt * 128 + lane;
#pragma unroll
            for (int ntp = 0; ntp < 4; ntp++) {
                uint4 Bv = bp[ntp * 32];
                mma_f16(d2[2 * ntp], A2[kt], Bv.x, Bv.y);
                mma_f16(d2[2 * ntp + 1], A2[kt], Bv.z, Bv.w);
            }
        }
        // swish -> h2 (fp32) to sH2 (warp-private rows)
        {
            float* hw0 = sH2 + row0 * PADH2;
            float* hw1 = hw0 + 8 * PADH2;
#pragma unroll
            for (int nt = 0; nt < 8; nt++) {
                int c = 8 * nt + 2 * tig;
                *reinterpret_cast<float2*>(hw0 + c) =
                    make_float2(swishf(d2[nt][0]), swishf(d2[nt][1]));
                *reinterpret_cast<float2*>(hw1 + c) =
                    make_float2(swishf(d2[nt][2]), swishf(d2[nt][3]));
            }
        }
        __syncwarp();   // h2 rows produced and consumed by this warp only

        // ============== W3 phase: M=16 per warp, fp16 K=256 ==============
        int l0 = 2 * (tig & 1);
        float2 ef0 = *reinterpret_cast<const float2*>(edge_features + (size_t)e0 * 4 + l0);
        float2 ef1 = *reinterpret_cast<const float2*>(edge_features + (size_t)e1 * 4 + l0);
        int snd0 = senders[e0], snd1 = senders[e1];
        int rcv0 = receivers[e0], rcv1 = receivers[e1];
        int mk0 = mask[e0], mk1 = mask[e1];

        float d3[8][4];
#pragma unroll
        for (int nt = 0; nt < 8; nt++)
#pragma unroll
            for (int q = 0; q < 4; q++) d3[nt][q] = 0.f;

        const float* hr0 = sH2 + row0 * PADH2;
        const float* hr1 = hr0 + 8 * PADH2;
        int koff = tig >> 1;
#pragma unroll
        for (int kt = 0; kt < 16; kt++) {
            int k0 = 4 * kt + koff;
            float h00 = hr0[k0];
            float h01 = hr0[k0 + 2];
            float h10 = hr1[k0];
            float h11 = hr1[k0 + 2];
            uint32_t A[4];
            A[0] = h2pack(h00 * ef0.x, h00 * ef0.y);   // row g,   k0, l pair
            A[1] = h2pack(h10 * ef1.x, h10 * ef1.y);   // row g+8, k0
            A[2] = h2pack(h01 * ef0.x, h01 * ef0.y);   // row g,   k1
            A[3] = h2pack(h11 * ef1.x, h11 * ef1.y);   // row g+8, k1
            const uint4* bp = sBf + kt * 128 + lane;
#pragma unroll
            for (int ntp = 0; ntp < 4; ntp++) {
                uint4 Bv = bp[ntp * 32];
                mma_f16(d3[2 * ntp], A, Bv.x, Bv.y);
                mma_f16(d3[2 * ntp + 1], A, Bv.z, Bv.w);
            }
        }

        // ---- epilogue: msg = d3 * x[snd], red-scatter to g_agg[rcv] ----
        if (mk0) {
            const float* xr = g_x + (size_t)snd0 * 64;
            float* ar = g_agg + (size_t)rcv0 * 64;
#pragma unroll
            for (int nt = 0; nt < 8; nt++) {
                int c = 8 * nt + 2 * tig;
                float2 xs = *reinterpret_cast<const float2*>(xr + c);
                red_add_f2(ar + c, d3[nt][0] * xs.x, d3[nt][1] * xs.y);
            }
        }
        if (mk1) {
            const float* xr = g_x + (size_t)snd1 * 64;
            float* ar = g_agg + (size_t)rcv1 * 64;
#pragma unroll
            for (int nt = 0; nt < 8; nt++) {
                int c = 8 * nt + 2 * tig;
                float2 xs = *reinterpret_cast<const float2*>(xr + c);
                red_add_f2(ar + c, d3[nt][2] * xs.x, d3[nt][3] * xs.y);
            }
        }
    }
}

// ---------------------------------------------------------------------------
// kernel_launch — edge_kernel at launch index 3 (profiler sample position);
// prep_kernel at idx 2, same stream => ordered before edge.
// ---------------------------------------------------------------------------
extern "C" void kernel_launch(void* const* d_in, const int* in_sizes, int n_in,
                              void* d_out, int out_size) {
    const float* node_features = (const float*)d_in[0];
    const float* edge_features = (const float*)d_in[1];
    const float* radial        = (const float*)d_in[2];
    const int*   senders       = (const int*)d_in[3];
    const int*   receivers     = (const int*)d_in[4];
    const int*   edge_mask     = (const int*)d_in[5];
    const float* W_up          = (const float*)d_in[6];
    const float* W1            = (const float*)d_in[7];
    const float* W2            = (const float*)d_in[8];
    const float* W3            = (const float*)d_in[9];
    const float* W_down        = (const float*)d_in[10];
    float*       out           = (float*)d_out;

    float* x_ptr = nullptr;
    float* agg_ptr = nullptr;
    cudaGetSymbolAddress((void**)&x_ptr, g_x);
    cudaGetSymbolAddress((void**)&agg_ptr, g_agg);

    // idx 0: x = node_features @ W_up
    linear64_kernel<<<(N_NODES + 127) / 128, 128>>>(node_features, W_up, x_ptr,
                                                    N_NODES, 1.0f);
    // idx 1: zero agg
    zero_agg_kernel<<<(N_NODES * FDIM / 4) / 256, 256>>>();
    // idx 2: one-time fp16 fragment repack (ordered before edge on stream)
    prep_kernel<<<5, 512>>>(W2, W3);
    // idx 3: fused edge kernel (multi-tile)  <-- profiler sample position
    cudaFuncSetAttribute(edge_kernel, cudaFuncAttributeMaxDynamicSharedMemorySize,
                         EDGE_SMEM);
    edge_kernel<<<N_EDGES / (TILE_E * TILES), NTH, EDGE_SMEM>>>(
        edge_features, radial, senders, receivers, edge_mask, W1);
    // idx 4: out = (agg / 16) @ W_down
    linear64_kernel<<<(N_NODES + 127) / 128, 128>>>(agg_ptr, W_down, out,
                                                    N_NODES, INV_AVG_NEIGH);
}